// round 17
// baseline (speedup 1.0000x reference)
#include <cuda_runtime.h>
#include <cuda_fp16.h>
#include <cstdint>

#define N_NODES  100000
#define N_EDGES  1600000
#define IN_CH    128
#define HID      256
#define OUT_CH   128
#define N_GRAPHS 2048

// ---------------- scratch (device globals: no allocation allowed) ----------------
__device__ int   g_deg[N_NODES];
__device__ int   g_fill[N_NODES];
__device__ int   g_rowptr[N_NODES + 1];
__device__ int   g_col[N_EDGES];
__device__ int   g_part[128];
__device__ int   g_part2[128];
__device__ int   g_gcnt[N_GRAPHS];
__device__ uint16_t g_A [(size_t)N_NODES * 512];     // fp16 A panel (stride 512)
__device__ uint16_t g_B1[256 * 512];                 // fp16 B panels (n-major, stride 512)
__device__ uint16_t g_B2[256 * 512];
__device__ uint16_t g_B3[256 * 512];
__device__ uint16_t g_B4[256 * 512];                 // rows 128..255 stay zero
__device__ float g_pool[N_GRAPHS * HID];

// ---------------- helpers ----------------
__device__ __forceinline__ uint16_t f16_bits(float v) {
    __half h = __float2half_rn(v);
    return *(uint16_t*)&h;
}
__device__ __forceinline__ uint32_t smem_u32(const void* p) {
    uint32_t a;
    asm("{ .reg .u64 t; cvta.to.shared.u64 t, %1; cvt.u32.u64 %0, t; }" : "=r"(a) : "l"(p));
    return a;
}

// ---------------- CSR build + zero ----------------
__global__ void zero_kernel() {
    int i = blockIdx.x * blockDim.x + threadIdx.x;
    if (i < N_NODES) { g_deg[i] = 0; g_fill[i] = 0; }
    if (i < N_GRAPHS * HID) g_pool[i] = 0.f;
    if (i < N_GRAPHS) g_gcnt[i] = 0;
}
__global__ void hist_kernel(const int* __restrict__ dst, const int* __restrict__ batch) {
    int e = blockIdx.x * blockDim.x + threadIdx.x;
    if (e < N_EDGES) atomicAdd(&g_deg[dst[e]], 1);
    if (e < N_NODES) atomicAdd(&g_gcnt[batch[e]], 1);
}
__global__ void scan1_kernel() {
    __shared__ int sh[1024];
    int t = threadIdx.x;
    int i = blockIdx.x * 1024 + t;
    sh[t] = (i < N_NODES) ? g_deg[i] : 0;
    __syncthreads();
    for (int off = 512; off > 0; off >>= 1) {
        if (t < off) sh[t] += sh[t + off];
        __syncthreads();
    }
    if (t == 0) g_part[blockIdx.x] = sh[0];
}
__global__ void scan2_kernel(int nparts) {
    __shared__ int sh[128];
    int t = threadIdx.x;
    int v = (t < nparts) ? g_part[t] : 0;
    sh[t] = v;
    __syncthreads();
    for (int off = 1; off < 128; off <<= 1) {
        int nv = (t >= off) ? sh[t - off] : 0;
        __syncthreads();
        sh[t] += nv;
        __syncthreads();
    }
    if (t < nparts) g_part2[t] = sh[t] - v;
    if (t == 0) g_rowptr[N_NODES] = N_EDGES;
}
__global__ void scan3_kernel() {
    __shared__ int sh[1024];
    int t = threadIdx.x;
    int i = blockIdx.x * 1024 + t;
    int v = (i < N_NODES) ? g_deg[i] : 0;
    sh[t] = v;
    __syncthreads();
    for (int off = 1; off < 1024; off <<= 1) {
        int nv = (t >= off) ? sh[t - off] : 0;
        __syncthreads();
        sh[t] += nv;
        __syncthreads();
    }
    if (i < N_NODES) g_rowptr[i] = sh[t] - v + g_part2[blockIdx.x];
}
__global__ void scatter_kernel(const int* __restrict__ src, const int* __restrict__ dst) {
    int e = blockIdx.x * blockDim.x + threadIdx.x;
    if (e >= N_EDGES) return;
    int d = dst[e];
    int p = g_rowptr[d] + atomicAdd(&g_fill[d], 1);
    g_col[p] = src[e];
}

// ---------------- fp16 writers / readers ----------------
__device__ __forceinline__ void h_store4(uint16_t* A, size_t base,
                                         float v0, float v1, float v2, float v3) {
    uint16_t h0 = f16_bits(v0), h1 = f16_bits(v1), h2 = f16_bits(v2), h3 = f16_bits(v3);
    *(uint2*)(A + base) = make_uint2((uint32_t)h0 | ((uint32_t)h1 << 16),
                                     (uint32_t)h2 | ((uint32_t)h3 << 16));
}
__device__ __forceinline__ void add4h(float* acc, uint2 h) {
    const uint32_t* hp = (const uint32_t*)&h;
#pragma unroll
    for (int i = 0; i < 2; i++) {
        __half2 hb = *(__half2*)&hp[i];
        float2 hf = __half22float2(hb);
        acc[i * 2]     += hf.x;
        acc[i * 2 + 1] += hf.y;
    }
}
__device__ __forceinline__ void add8h(float* acc, uint4 h) {
    const uint32_t* hp = (const uint32_t*)&h;
#pragma unroll
    for (int i = 0; i < 4; i++) {
        __half2 hb = *(__half2*)&hp[i];
        float2 hf = __half22float2(hb);
        acc[i * 2]     += hf.x;
        acc[i * 2 + 1] += hf.y;
    }
}

// layer-1 mean aggregation: gathers fp16 x (panel cols 128..255), 8/4-way edge unroll
__global__ void agg1_kernel(const uint16_t* __restrict__ Ap, uint16_t* __restrict__ A) {
    int w = (blockIdx.x * blockDim.x + threadIdx.x) >> 5;
    int lane = threadIdx.x & 31;
    if (w >= N_NODES) return;
    int beg = g_rowptr[w], end = g_rowptr[w + 1];
    float acc[4];
#pragma unroll
    for (int i = 0; i < 4; i++) acc[i] = 0.f;
    int j = beg;
    for (; j + 7 < end; j += 8) {
        uint2 h[8];
#pragma unroll
        for (int q = 0; q < 8; q++)
            h[q] = *(const uint2*)(Ap + (size_t)g_col[j + q] * 512 + 128 + lane * 4);
#pragma unroll
        for (int q = 0; q < 8; q++) add4h(acc, h[q]);
    }
    if (j + 3 < end) {
        uint2 h[4];
#pragma unroll
        for (int q = 0; q < 4; q++)
            h[q] = *(const uint2*)(Ap + (size_t)g_col[j + q] * 512 + 128 + lane * 4);
#pragma unroll
        for (int q = 0; q < 4; q++) add4h(acc, h[q]);
        j += 4;
    }
    for (; j < end; j++) {
        uint2 h0 = *(const uint2*)(Ap + (size_t)g_col[j] * 512 + 128 + lane * 4);
        add4h(acc, h0);
    }
    float inv = (end > beg) ? 1.f / (float)(end - beg) : 0.f;
    h_store4(A, (size_t)w * 512 + (size_t)lane * 4,
             acc[0] * inv, acc[1] * inv, acc[2] * inv, acc[3] * inv);
}

// layer-2 mean aggregation: gathers fp16 h1 (panel cols 256..511), 8/4-way edge unroll
__global__ void agg2_kernel(const uint16_t* __restrict__ Ap, uint16_t* __restrict__ A) {
    int w = (blockIdx.x * blockDim.x + threadIdx.x) >> 5;
    int lane = threadIdx.x & 31;
    if (w >= N_NODES) return;
    int beg = g_rowptr[w], end = g_rowptr[w + 1];
    float acc[8];
#pragma unroll
    for (int i = 0; i < 8; i++) acc[i] = 0.f;
    int j = beg;
    for (; j + 7 < end; j += 8) {
        uint4 h[8];
#pragma unroll
        for (int q = 0; q < 8; q++)
            h[q] = *(const uint4*)(Ap + (size_t)g_col[j + q] * 512 + 256 + lane * 8);
#pragma unroll
        for (int q = 0; q < 8; q++) add8h(acc, h[q]);
    }
    if (j + 3 < end) {
        uint4 h[4];
#pragma unroll
        for (int q = 0; q < 4; q++)
            h[q] = *(const uint4*)(Ap + (size_t)g_col[j + q] * 512 + 256 + lane * 8);
#pragma unroll
        for (int q = 0; q < 4; q++) add8h(acc, h[q]);
        j += 4;
    }
    for (; j < end; j++) {
        uint4 h0 = *(const uint4*)(Ap + (size_t)g_col[j] * 512 + 256 + lane * 8);
        add8h(acc, h0);
    }
    float inv = (end > beg) ? 1.f / (float)(end - beg) : 0.f;
    size_t base = (size_t)w * 512 + (size_t)lane * 8;
    h_store4(A, base,     acc[0] * inv, acc[1] * inv, acc[2] * inv, acc[3] * inv);
    h_store4(A, base + 4, acc[4] * inv, acc[5] * inv, acc[6] * inv, acc[7] * inv);
}

// convert x (fp32 [N,128]) into A panel cols 128..255
__global__ void xconv_kernel(const float* __restrict__ x, uint16_t* __restrict__ A) {
    int idx = blockIdx.x * blockDim.x + threadIdx.x;
    if (idx >= N_NODES * 32) return;
    int row = idx >> 5, q = idx & 31;
    float4 v = ((const float4*)x)[idx];
    h_store4(A, (size_t)row * 512 + 128 + (size_t)q * 4, v.x, v.y, v.z, v.w);
}

// transpose + convert weight W[Kw,Nout] into B panel rows n<Nout
__global__ void wconv_kernel(const float* __restrict__ W, int Kw, int Nout, int cofs,
                             uint16_t* __restrict__ B) {
    int idx = blockIdx.x * blockDim.x + threadIdx.x;
    if (idx >= Nout * Kw) return;
    int n = idx / Kw, k = idx - n * Kw;
    B[(size_t)n * 512 + cofs + k] = f16_bits(W[(size_t)k * Nout + n]);
}

// ---------------- single-pass fp16 HMMA GEMM, K-chunk = 64, double-buffered smem ----------------
#define LDB_S 72         // smem row stride in fp16 elems (144B): ldmatrix conflict-free
#define STAGE_B 36864    // bytes per stage (As 18432 + Bs 18432)

__device__ __forceinline__ void mma_f16(float* c, const uint32_t* a, const uint32_t* b) {
    asm volatile(
        "mma.sync.aligned.m16n8k16.row.col.f32.f16.f16.f32 "
        "{%0,%1,%2,%3}, {%4,%5,%6,%7}, {%8,%9}, {%0,%1,%2,%3};"
        : "+f"(c[0]), "+f"(c[1]), "+f"(c[2]), "+f"(c[3])
        : "r"(a[0]), "r"(a[1]), "r"(a[2]), "r"(a[3]), "r"(b[0]), "r"(b[1]));
}
__device__ __forceinline__ void ldsm_x4(uint32_t* r, uint32_t addr) {
    asm volatile("ldmatrix.sync.aligned.m8n8.x4.shared.b16 {%0,%1,%2,%3}, [%4];"
                 : "=r"(r[0]), "=r"(r[1]), "=r"(r[2]), "=r"(r[3]) : "r"(addr));
}

__global__ __launch_bounds__(256) void hgemm_kernel(
    const uint16_t* __restrict__ A, const uint16_t* __restrict__ B,
    int K, const float* __restrict__ bias,
    uint16_t* __restrict__ oA,            // fp16 panel out (cols 256..511) or nullptr
    float* __restrict__ Cf, int ldc,      // fp32 out or nullptr
    int do_relu, int M,
    const int* __restrict__ batchp, float* __restrict__ psum, int fuse_pool)
{
    extern __shared__ __align__(16) uint8_t smraw[];   // 2 * STAGE_B

    const int tid = threadIdx.x;
    const int lane = tid & 31, wid = tid >> 5;
    const int wm = wid & 3, wn = wid >> 2;
    const int g = lane >> 2, th = lane & 3;
    const int row0 = blockIdx.x * 128;
    const int n0 = blockIdx.y * 128;

    const uint32_t sbase = smem_u32(smraw);
    const int nch = K >> 6;   // K multiple of 64 (256 or 512)

    float acc[2][8][4];
#pragma unroll
    for (int mt = 0; mt < 2; mt++)
#pragma unroll
        for (int nt = 0; nt < 8; nt++)
#pragma unroll
            for (int r = 0; r < 4; r++) acc[mt][nt][r] = 0.f;

    const int lt = lane >> 3, lr = lane & 7;

    uint4 ra[4], rb[4];
    // prologue: load chunk 0 and store into stage 0
    {
#pragma unroll
        for (int i = 0; i < 4; i++) {
            int u = tid + i * 256;
            int r = u >> 3, q = u & 7;
            int ga = row0 + r;
            ra[i] = (ga < M) ? *(const uint4*)(A + (size_t)ga * 512 + q * 8)
                             : make_uint4(0, 0, 0, 0);
            rb[i] = *(const uint4*)(B + (size_t)(n0 + r) * 512 + q * 8);
        }
        uint16_t* As = (uint16_t*)(smraw);
        uint16_t* Bs = (uint16_t*)(smraw + 18432);
#pragma unroll
        for (int i = 0; i < 4; i++) {
            int u = tid + i * 256;
            int r = u >> 3, q = u & 7;
            int so = r * LDB_S + q * 8;
            *(uint4*)&As[so] = ra[i];
            *(uint4*)&Bs[so] = rb[i];
        }
        __syncthreads();
    }

#pragma unroll 1
    for (int c = 0; c < nch; c++) {
        int s = c & 1;
        // prefetch chunk c+1 and store into the other stage (safe: protected by
        // the barrier at the end of iteration c-1)
        if (c + 1 < nch) {
            int kb = (c + 1) * 64;
#pragma unroll
            for (int i = 0; i < 4; i++) {
                int u = tid + i * 256;
                int r = u >> 3, q = u & 7;
                int ga = row0 + r;
                ra[i] = (ga < M) ? *(const uint4*)(A + (size_t)ga * 512 + kb + q * 8)
                                 : make_uint4(0, 0, 0, 0);
                rb[i] = *(const uint4*)(B + (size_t)(n0 + r) * 512 + kb + q * 8);
            }
            uint16_t* As = (uint16_t*)(smraw + (s ^ 1) * STAGE_B);
            uint16_t* Bs = (uint16_t*)(smraw + (s ^ 1) * STAGE_B + 18432);
#pragma unroll
            for (int i = 0; i < 4; i++) {
                int u = tid + i * 256;
                int r = u >> 3, q = u & 7;
                int so = r * LDB_S + q * 8;
                *(uint4*)&As[so] = ra[i];
                *(uint4*)&Bs[so] = rb[i];
            }
        }

        const uint32_t sA = sbase + s * STAGE_B;
        const uint32_t sB = sA + 18432;
#pragma unroll
        for (int step = 0; step < 4; step++) {
            const int k0 = step * 16;
            uint32_t aoff[2];
#pragma unroll
            for (int mt = 0; mt < 2; mt++) {
                int ar = wm * 32 + mt * 16 + (lt & 1) * 8 + lr;
                int ak = k0 + (lt >> 1) * 8;
                aoff[mt] = (uint32_t)(ar * LDB_S + ak) * 2;
            }
            uint32_t boff[4];
#pragma unroll
            for (int ntp = 0; ntp < 4; ntp++) {
                int nr = wn * 64 + ntp * 16 + (lt >> 1) * 8 + lr;
                int nk = k0 + (lt & 1) * 8;
                boff[ntp] = (uint32_t)(nr * LDB_S + nk) * 2;
            }

            uint32_t ah[2][4], bh[4][4];
#pragma unroll
            for (int mt = 0; mt < 2; mt++) ldsm_x4(ah[mt], sA + aoff[mt]);
#pragma unroll
            for (int ntp = 0; ntp < 4; ntp++) ldsm_x4(bh[ntp], sB + boff[ntp]);
#pragma unroll
            for (int mt = 0; mt < 2; mt++)
#pragma unroll
                for (int nt = 0; nt < 8; nt++)
                    mma_f16(acc[mt][nt], ah[mt], &bh[nt >> 1][(nt & 1) * 2]);
        }
        __syncthreads();
    }

    if (!fuse_pool) {
#pragma unroll
        for (int mt = 0; mt < 2; mt++) {
            int rbase = row0 + wm * 32 + mt * 16 + g;
#pragma unroll
            for (int nt = 0; nt < 8; nt++) {
                int col = n0 + wn * 64 + nt * 8 + th * 2;
                float bx = bias[col], by = bias[col + 1];
                float2 v0 = make_float2(acc[mt][nt][0] + bx, acc[mt][nt][1] + by);
                float2 v1 = make_float2(acc[mt][nt][2] + bx, acc[mt][nt][3] + by);
                if (do_relu) {
                    v0.x = fmaxf(v0.x, 0.f); v0.y = fmaxf(v0.y, 0.f);
                    v1.x = fmaxf(v1.x, 0.f); v1.y = fmaxf(v1.y, 0.f);
                }
                if (rbase < M) {
                    if (oA) {
                        uint16_t h0 = f16_bits(v0.x), h1 = f16_bits(v0.y);
                        *(uint32_t*)(oA + (size_t)rbase * 512 + 256 + col) =
                            (uint32_t)h0 | ((uint32_t)h1 << 16);
                    }
                    if (Cf) *(float2*)(Cf + (size_t)rbase * ldc + col) = v0;
                }
                if (rbase + 8 < M) {
                    if (oA) {
                        uint16_t h0 = f16_bits(v1.x), h1 = f16_bits(v1.y);
                        *(uint32_t*)(oA + (size_t)(rbase + 8) * 512 + 256 + col) =
                            (uint32_t)h0 | ((uint32_t)h1 << 16);
                    }
                    if (Cf) *(float2*)(Cf + (size_t)(rbase + 8) * ldc + col) = v1;
                }
            }
        }
    } else {
        float* red = (float*)smraw;              // [128][66] = 33792B <= 2*STAGE_B
        __shared__ int sbat[128];
#pragma unroll 1
        for (int h = 0; h < 2; h++) {
            __syncthreads();
            if (tid < 128) sbat[tid] = (row0 + tid < M) ? batchp[row0 + tid] : -1;
            if (wn == h) {
#pragma unroll
                for (int mt = 0; mt < 2; mt++) {
                    int rl = wm * 32 + mt * 16 + g;
#pragma unroll
                    for (int nt = 0; nt < 8; nt++) {
                        int cl = nt * 8 + th * 2;
                        int colg = n0 + h * 64 + cl;
                        float bx = bias[colg], by = bias[colg + 1];
                        red[rl * 66 + cl]       = fmaxf(acc[mt][nt][0] + bx, 0.f);
                        red[rl * 66 + cl + 1]   = fmaxf(acc[mt][nt][1] + by, 0.f);
                        red[(rl + 8) * 66 + cl]     = fmaxf(acc[mt][nt][2] + bx, 0.f);
                        red[(rl + 8) * 66 + cl + 1] = fmaxf(acc[mt][nt][3] + by, 0.f);
                    }
                }
            }
            __syncthreads();
            int cl = tid & 63, rh = tid >> 6;
            float run = 0.f; int cur = -1;
#pragma unroll 1
            for (int r = rh * 32; r < rh * 32 + 32; r++) {
                int gb = sbat[r];
                if (gb != cur) {
                    if (cur >= 0)
                        atomicAdd(&psum[(size_t)cur * 256 + n0 + h * 64 + cl], run);
                    run = 0.f; cur = gb;
                }
                if (gb >= 0) run += red[r * 66 + cl];
            }
            if (cur >= 0)
                atomicAdd(&psum[(size_t)cur * 256 + n0 + h * 64 + cl], run);
        }
    }
}

// ---------------- finalize pooled means: write fp16 into A panel rows 0..2047, cols 0..255
__global__ void finalize_kernel(uint16_t* __restrict__ A) {
    int i = blockIdx.x * blockDim.x + threadIdx.x;
    if (i >= N_GRAPHS * HID) return;
    int gidx = i >> 8, c = i & 255;
    float cnt = (float)g_gcnt[gidx];
    float v = g_pool[i] / fmaxf(cnt, 1.f);
    A[(size_t)gidx * 512 + c] = f16_bits(v);
}

// ---------------- launch ----------------
extern "C" void kernel_launch(void* const* d_in, const int* in_sizes, int n_in,
                              void* d_out, int out_size) {
    const float* x   = (const float*)d_in[0];
    const int*   ei  = (const int*)d_in[1];
    const int*   src = ei;
    const int*   dst = ei + N_EDGES;
    const int* batch = (const int*)d_in[2];
    const float* W1l = (const float*)d_in[3];
    const float* b1  = (const float*)d_in[4];
    const float* W1r = (const float*)d_in[5];
    const float* W2l = (const float*)d_in[6];
    const float* b2  = (const float*)d_in[7];
    const float* W2r = (const float*)d_in[8];
    const float* W3  = (const float*)d_in[9];
    const float* b3  = (const float*)d_in[10];
    const float* W4  = (const float*)d_in[11];
    const float* b4  = (const float*)d_in[12];
    float* out = (float*)d_out;

    void *p_pool, *p_A, *p_B1, *p_B2, *p_B3, *p_B4;
    cudaGetSymbolAddress(&p_pool, g_pool);
    cudaGetSymbolAddress(&p_A, g_A);
    cudaGetSymbolAddress(&p_B1, g_B1);
    cudaGetSymbolAddress(&p_B2, g_B2);
    cudaGetSymbolAddress(&p_B3, g_B3);
    cudaGetSymbolAddress(&p_B4, g_B4);
    float* pooled = (float*)p_pool;
    uint16_t* A  = (uint16_t*)p_A;
    uint16_t* B1 = (uint16_t*)p_B1;
    uint16_t* B2 = (uint16_t*)p_B2;
    uint16_t* B3 = (uint16_t*)p_B3;
    uint16_t* B4 = (uint16_t*)p_B4;

    static cudaStream_t s_aux = nullptr;
    static cudaEvent_t ev_fork = nullptr, ev_join = nullptr;
    if (!s_aux) {
        cudaStreamCreateWithFlags(&s_aux, cudaStreamNonBlocking);
        cudaEventCreateWithFlags(&ev_fork, cudaEventDisableTiming);
        cudaEventCreateWithFlags(&ev_join, cudaEventDisableTiming);
        cudaFuncSetAttribute(hgemm_kernel, cudaFuncAttributeMaxDynamicSharedMemorySize,
                             2 * STAGE_B);
    }

    const int TB = 256;
    const dim3 ggrid((N_NODES + 127) / 128, 2);
    const int NSCAN = (N_NODES + 1023) / 1024;
    const int DSM = 2 * STAGE_B;

    // ---- fork: weight/x conversions on aux stream ----
    cudaEventRecord(ev_fork, 0);
    cudaStreamWaitEvent(s_aux, ev_fork, 0);
    xconv_kernel<<<(N_NODES * 32 + TB - 1) / TB, TB, 0, s_aux>>>(x, A);
    wconv_kernel<<<(256 * 128 + TB - 1) / TB, TB, 0, s_aux>>>(W1l, 128, 256, 0, B1);
    wconv_kernel<<<(256 * 128 + TB - 1) / TB, TB, 0, s_aux>>>(W1r, 128, 256, 128, B1);
    wconv_kernel<<<(256 * 256 + TB - 1) / TB, TB, 0, s_aux>>>(W2l, 256, 256, 0, B2);
    wconv_kernel<<<(256 * 256 + TB - 1) / TB, TB, 0, s_aux>>>(W2r, 256, 256, 256, B2);
    wconv_kernel<<<(256 * 256 + TB - 1) / TB, TB, 0, s_aux>>>(W3, 256, 256, 0, B3);
    wconv_kernel<<<(128 * 256 + TB - 1) / TB, TB, 0, s_aux>>>(W4, 256, 128, 0, B4);
    cudaEventRecord(ev_join, s_aux);

    // ---- main stream: CSR build + zero pooled sums ----
    zero_kernel<<<(N_GRAPHS * HID + TB - 1) / TB, TB>>>();
    hist_kernel<<<(N_EDGES + TB - 1) / TB, TB>>>(dst, batch);
    scan1_kernel<<<NSCAN, 1024>>>();
    scan2_kernel<<<1, 128>>>(NSCAN);
    scan3_kernel<<<NSCAN, 1024>>>();
    scatter_kernel<<<(N_EDGES + TB - 1) / TB, TB>>>(src, dst);

    // join before agg1 (needs x fp16 panel)
    cudaStreamWaitEvent(0, ev_join, 0);

    // Layer 1: agg over fp16-x panel (cols 128..255) -> cols 0..127; gemm1 K=256
    agg1_kernel<<<(N_NODES * 32 + TB - 1) / TB, TB>>>(A, A);
    hgemm_kernel<<<ggrid, 256, DSM>>>(A, B1, 256, b1, A, nullptr, 0, 1, N_NODES,
                                      nullptr, nullptr, 0);

    // Layer 2: agg over fp16-h1 panel (cols 256..511) -> cols 0..255; fused-pool GEMM K=512
    agg2_kernel<<<(N_NODES * 32 + TB - 1) / TB, TB>>>(A, A);
    hgemm_kernel<<<ggrid, 256, DSM>>>(A, B2, 512, b2, nullptr, nullptr, 0, 1, N_NODES,
                                      batch, pooled, 1);

    // pooled means (fp16 into A panel rows 0..2047, cols 0..255)
    finalize_kernel<<<(N_GRAPHS * HID + TB - 1) / TB, TB>>>(A);

    // MLP head on fp16 HMMA path
    {
        dim3 grid((N_GRAPHS + 127) / 128, 2);
        hgemm_kernel<<<grid, 256, DSM>>>(A, B3, 256, b3, A, nullptr, 0, 1, N_GRAPHS,
                                         nullptr, nullptr, 0);   // hidden fp16 -> cols 256..511
    }
    {
        dim3 grid((N_GRAPHS + 127) / 128, 1);
        hgemm_kernel<<<grid, 256, DSM>>>(A + 256, B4, 256, b4, nullptr, out, 128, 0,
                                         N_GRAPHS, nullptr, nullptr, 0);
    }
}